// round 17
// baseline (speedup 1.0000x reference)
#include <cuda_runtime.h>

#define DIMX   240
#define NTYPE  10
#define EPSV   1e-5f
#define MAXB   200704
#define RPB    256   // rows per reduce block
#define RU     4     // unroll (both paths)

__device__ float g_sum[NTYPE * 64];    // scalar-channel sums
__device__ float g_sq[NTYPE * DIMX];   // per-column sum of squares
__device__ int   g_cnti[NTYPE];
__device__ int   g_cursor[NTYPE];
__device__ int   g_perm[MAXB];
__device__ float g_A[NTYPE * DIMX];
__device__ float g_C[NTYPE * DIMX];
__device__ unsigned g_done = 0;

__global__ void k_zero() {
    int i = threadIdx.x;
    if (i < NTYPE) { g_cnti[i] = 0; g_cursor[i] = 0; }
}

__global__ void k_hist(const int* __restrict__ tp, int batch) {
    __shared__ int h[NTYPE];
    if (threadIdx.x < NTYPE) h[threadIdx.x] = 0;
    __syncthreads();
    for (int i = blockIdx.x * blockDim.x + threadIdx.x; i < batch;
         i += gridDim.x * blockDim.x) {
        atomicAdd(&h[tp[i]], 1);
    }
    __syncthreads();
    if (threadIdx.x < NTYPE) atomicAdd(&g_cnti[threadIdx.x], h[threadIdx.x]);
}

// Counting-sort scatter (inline 10-element scan of g_cnti). Also zeroes the
// accumulators (stream order guarantees this precedes k_reduce).
__global__ void k_scatter(const int* __restrict__ tp, int batch) {
    __shared__ int h[NTYPE], base[NTYPE], soff[NTYPE];
    const int gi = blockIdx.x * blockDim.x + threadIdx.x;
    if (gi < NTYPE * DIMX) g_sq[gi] = 0.0f;
    if (gi < NTYPE * 64) g_sum[gi] = 0.0f;
    if (threadIdx.x < NTYPE) {
        h[threadIdx.x] = 0;
        int o = 0;
        for (int k = 0; k < threadIdx.x; k++) o += g_cnti[k];
        soff[threadIdx.x] = o;
    }
    __syncthreads();
    int t = 0, loc = 0;
    if (gi < batch) {
        t = tp[gi];
        loc = atomicAdd(&h[t], 1);
    }
    __syncthreads();
    if (threadIdx.x < NTYPE && h[threadIdx.x] > 0)
        base[threadIdx.x] = soff[threadIdx.x] + atomicAdd(&g_cursor[threadIdx.x], h[threadIdx.x]);
    __syncthreads();
    if (gi < batch) g_perm[base[t] + loc] = gi;
}

__device__ __forceinline__ void flush_acc(int t, int q, bool sc,
                                          float* ssq, float* ssm) {
    float* gq = g_sq + t * DIMX + q * 4;
    atomicAdd(gq + 0, ssq[0]);
    atomicAdd(gq + 1, ssq[1]);
    atomicAdd(gq + 2, ssq[2]);
    atomicAdd(gq + 3, ssq[3]);
    ssq[0] = ssq[1] = ssq[2] = ssq[3] = 0.f;
    if (sc) {
        float* gs = g_sum + t * 64 + q * 4;
        atomicAdd(gs + 0, ssm[0]);
        atomicAdd(gs + 1, ssm[1]);
        atomicAdd(gs + 2, ssm[2]);
        atomicAdd(gs + 3, ssm[3]);
        ssm[0] = ssm[1] = ssm[2] = ssm[3] = 0.f;
    }
}

// float4 reduce over bucket-sorted rows + last-block stats (g_A/g_C).
// Tile = 4 rows; thread (r,q) owns float4 q of row r. Single wave (<=888 slots).
__global__ void __launch_bounds__(256, 6)
k_reduce(const float4* __restrict__ x4, const float* __restrict__ w,
         const float* __restrict__ b, int batch, int ngrid) {
    __shared__ int soff[NTYPE + 1];
    __shared__ int sperm[RPB];
    __shared__ bool slast;
    const int tid = threadIdx.x;
    if (tid < NTYPE) {
        int o = 0;
        for (int k = 0; k < tid; k++) o += g_cnti[k];
        soff[tid] = o;
    }
    if (tid == NTYPE) soff[NTYPE] = batch;
    const int row0 = blockIdx.x * RPB;
    const int nrows = min(RPB, batch - row0);
    for (int j = tid; j < nrows; j += 256) sperm[j] = g_perm[row0 + j];
    __syncthreads();

    const int r = tid / 60;
    const int q = tid - r * 60;
    const bool sc = (q < 16);   // scalar quad (cols 0..63)

    if (tid < 240 && row0 + r < batch) {
        int tA = 0;
        while (row0 >= soff[tA + 1]) tA++;
        int tB = tA;
        while (row0 + nrows - 1 >= soff[tB + 1]) tB++;

        float ssq[4] = {0.f, 0.f, 0.f, 0.f};
        float ssm[4] = {0.f, 0.f, 0.f, 0.f};

        if (tA == tB && nrows == RPB) {
            // ---- fast path: single type, full block ----
#pragma unroll 1
            for (int j0 = 0; j0 < RPB / 4; j0 += RU) {
                float4 v[RU];
#pragma unroll
                for (int u = 0; u < RU; u++) {
                    const unsigned row = (unsigned)sperm[(j0 + u) * 4 + r];
                    v[u] = x4[row * 60u + (unsigned)q];
                }
#pragma unroll
                for (int u = 0; u < RU; u++) {
                    ssq[0] = fmaf(v[u].x, v[u].x, ssq[0]);
                    ssq[1] = fmaf(v[u].y, v[u].y, ssq[1]);
                    ssq[2] = fmaf(v[u].z, v[u].z, ssq[2]);
                    ssq[3] = fmaf(v[u].w, v[u].w, ssq[3]);
                    if (sc) {
                        ssm[0] += v[u].x;
                        ssm[1] += v[u].y;
                        ssm[2] += v[u].z;
                        ssm[3] += v[u].w;
                    }
                }
            }
            flush_acc(tA, q, sc, ssq, ssm);
        } else {
            // ---- slow path: boundary or partial block ----
            int curt = tA;
            const int p0 = row0 + r;
            while (p0 >= soff[curt + 1]) curt++;

            for (int tb = 0; tb < RPB / 4; tb += RU) {
                float4 v[RU];
                bool ok[RU];
#pragma unroll
                for (int u = 0; u < RU; u++) {
                    const int j = (tb + u) * 4 + r;
                    ok[u] = (j < nrows);
                    if (ok[u]) {
                        const unsigned row = (unsigned)sperm[j];
                        v[u] = x4[row * 60u + (unsigned)q];
                    }
                }
#pragma unroll
                for (int u = 0; u < RU; u++) {
                    if (!ok[u]) continue;
                    const int p = row0 + (tb + u) * 4 + r;
                    if (p >= soff[curt + 1]) {
                        flush_acc(curt, q, sc, ssq, ssm);
                        while (p >= soff[curt + 1]) curt++;
                    }
                    ssq[0] = fmaf(v[u].x, v[u].x, ssq[0]);
                    ssq[1] = fmaf(v[u].y, v[u].y, ssq[1]);
                    ssq[2] = fmaf(v[u].z, v[u].z, ssq[2]);
                    ssq[3] = fmaf(v[u].w, v[u].w, ssq[3]);
                    if (sc) {
                        ssm[0] += v[u].x;
                        ssm[1] += v[u].y;
                        ssm[2] += v[u].z;
                        ssm[3] += v[u].w;
                    }
                }
            }
            flush_acc(curt, q, sc, ssq, ssm);
        }
    }

    // ---- last-block stats: compute g_A/g_C once all accumulators landed ----
    __threadfence();
    __syncthreads();
    if (tid == 0) {
        unsigned v = atomicAdd(&g_done, 1u);
        slast = (v == (unsigned)(ngrid - 1));
    }
    __syncthreads();
    if (!slast) return;

    if (tid < 240) {
        const int c = tid;
#pragma unroll 1
        for (int t = 0; t < NTYPE; t++) {
            const float cnt = fmaxf((float)g_cnti[t], 1.0f);
            const float* sq = g_sq + t * DIMX;
            float A, C;
            if (c < 64) {
                const float fm  = g_sum[t * 64 + c] / cnt;
                const float var = sq[c] / cnt - fm * fm;
                const float s   = rsqrtf(var + EPSV) * w[t * 112 + c];
                A = s;
                C = b[t * 64 + c] - fm * s;
            } else if (c < 160) {
                const int m = (c - 64) / 3;
                const int base = 64 + 3 * m;
                const float fn = (sq[base] + sq[base + 1] + sq[base + 2]) / (3.0f * cnt);
                A = rsqrtf(fn + EPSV) * w[t * 112 + 64 + m];
                C = 0.0f;
            } else {
                const int m = (c - 160) / 5;
                const int base = 160 + 5 * m;
                const float fn = (sq[base] + sq[base + 1] + sq[base + 2] + sq[base + 3] + sq[base + 4])
                                 / (5.0f * cnt);
                A = rsqrtf(fn + EPSV) * w[t * 112 + 96 + m];
                C = 0.0f;
            }
            g_A[t * DIMX + c] = A;
            g_C[t * DIMX + c] = C;
        }
    }
    if (tid == 0) g_done = 0;   // self-reset for next graph replay
}

// out = x * A[type][col] + C[type][col]; 4-row tiles, U=4 unroll, loads batched.
#define UAPP 4
__global__ void __launch_bounds__(240)
k_apply(const float4* __restrict__ x4, const int* __restrict__ tp,
        float4* __restrict__ o4, int batch) {
    __shared__ __align__(16) float sA[NTYPE * DIMX];
    __shared__ __align__(16) float sC[NTYPE * DIMX];
    const int tid = threadIdx.x;
    {
        const float4* gA4 = (const float4*)g_A;
        const float4* gC4 = (const float4*)g_C;
        float4* sA4 = (float4*)sA;
        float4* sC4 = (float4*)sC;
#pragma unroll
        for (int i = 0; i < 3; i++) {
            const int j = tid + i * 240;
            if (j < NTYPE * DIMX / 4) {
                sA4[j] = gA4[j];
                sC4[j] = gC4[j];
            }
        }
    }
    __syncthreads();

    const int r = tid / 60;
    const int q = tid - r * 60;
    const int ntiles = (batch + 3) >> 2;
    const int ngrp = (ntiles + UAPP - 1) / UAPP;

    for (int g = blockIdx.x; g < ngrp; g += gridDim.x) {
        const int tile0 = g * UAPP;
        float4 xv[UAPP];
        int t[UAPP];
        bool ok[UAPP];
#pragma unroll
        for (int u = 0; u < UAPP; u++) {
            const int tile = tile0 + u;
            const int row = tile * 4 + r;
            ok[u] = (row < batch);
            if (ok[u]) {
                xv[u] = x4[(unsigned)tile * 240u + (unsigned)tid];
                t[u] = __ldg(tp + row);
            }
        }
#pragma unroll
        for (int u = 0; u < UAPP; u++) {
            if (ok[u]) {
                const int tile = tile0 + u;
                const float4 a  = *((const float4*)(sA + t[u] * DIMX) + q);
                const float4 cc = *((const float4*)(sC + t[u] * DIMX) + q);
                float4 res;
                res.x = fmaf(xv[u].x, a.x, cc.x);
                res.y = fmaf(xv[u].y, a.y, cc.y);
                res.z = fmaf(xv[u].z, a.z, cc.z);
                res.w = fmaf(xv[u].w, a.w, cc.w);
                o4[(unsigned)tile * 240u + (unsigned)tid] = res;
            }
        }
    }
}

extern "C" void kernel_launch(void* const* d_in, const int* in_sizes, int n_in,
                              void* d_out, int out_size) {
    const float* x  = (const float*)d_in[0];
    const int*   tp = (const int*)d_in[1];
    const float* w  = (const float*)d_in[2];
    const float* b  = (const float*)d_in[3];
    float* out = (float*)d_out;
    const int batch = in_sizes[1];

    const int nred = (batch + RPB - 1) / RPB;
    k_zero<<<1, 32>>>();
    k_hist<<<296, 256>>>(tp, batch);
    k_scatter<<<(batch + 255) / 256, 256>>>(tp, batch);
    k_reduce<<<nred, 256>>>((const float4*)x, w, b, batch, nred);
    k_apply<<<1184, 240>>>((const float4*)x, tp, (float4*)out, batch);
}